// round 1
// baseline (speedup 1.0000x reference)
#include <cuda_runtime.h>
#include <math.h>

typedef unsigned long long u64;

// ---- packed f32x2 FMA helpers (Blackwell sm_100+) ----
__device__ __forceinline__ u64 dup2(float x) {
    u64 r; asm("mov.b64 %0, {%1,%2};" : "=l"(r) : "f"(x), "f"(x)); return r;
}
__device__ __forceinline__ u64 ffma2(u64 a, u64 b, u64 c) {
    u64 d; asm("fma.rn.f32x2 %0, %1, %2, %3;" : "=l"(d) : "l"(a), "l"(b), "l"(c)); return d;
}
__device__ __forceinline__ float2 unpack2(u64 v) {
    float2 f; asm("mov.b64 {%0,%1}, %2;" : "=f"(f.x), "=f"(f.y) : "l"(v)); return f;
}

#define T_SEQ 200
#define BATCH 128
#define MROWS (T_SEQ * BATCH)   // 25600

// ---- device-global scratch (no allocations allowed) ----
__device__ float g_x0[MROWS * 400];             // embedded input, 41 MB
__device__ float g_xg[(size_t)MROWS * 4600];    // per-layer xg buffer, 471 MB
__device__ float g_c[BATCH * 1150];             // LSTM cell state
__device__ float g_h0[BATCH * 1150];            // zero h for t=0

// ---------------------------------------------------------------------------
__global__ void zero_kernel(float* __restrict__ p, int n) {
    int i = blockIdx.x * blockDim.x + threadIdx.x;
    if (i < n) p[i] = 0.0f;
}

// ---------------------------------------------------------------------------
__global__ void embed_kernel(const int* __restrict__ tokens,
                             const float* __restrict__ emb,
                             float* __restrict__ x) {
    int row = blockIdx.x;            // 0..25599
    int tok = tokens[row];
    const float4* s = (const float4*)(emb + (size_t)tok * 400);
    float4* d = (float4*)(x + (size_t)row * 400);
    for (int i = threadIdx.x; i < 100; i += blockDim.x) d[i] = s[i];
}

// ---------------------------------------------------------------------------
// C[M,N] = A[M,K] @ W[N,K]^T + bias[N]
// 128x128 block tile, BK=16, 256 threads, 8x8 per thread, f32x2 packed FMA.
#define BK 16
__global__ __launch_bounds__(256) void sgemm_nt_bias(
    const float* __restrict__ A, const float* __restrict__ W,
    const float* __restrict__ bias, float* __restrict__ C,
    int M, int N, int K)
{
    __shared__ float As[BK * 132];
    __shared__ float Bs[BK * 132];

    const int tid = threadIdx.x;
    const int m0 = blockIdx.y * 128;
    const int n0 = blockIdx.x * 128;
    const int tx = tid & 15;       // col group (interleaved cols: tx + 16*c)
    const int ty = tid >> 4;       // row group (rows ty*8 .. ty*8+7)
    const int lk = tid & 15;       // loader k
    const int lr = tid >> 4;       // loader row base

    u64 acc[4][8];
#pragma unroll
    for (int p = 0; p < 4; ++p)
#pragma unroll
        for (int c = 0; c < 8; ++c) acc[p][c] = 0ull;

    for (int k0 = 0; k0 < K; k0 += BK) {
        const int k = k0 + lk;
        const bool kin = (k < K);
#pragma unroll
        for (int p = 0; p < 8; ++p) {
            int row = lr + p * 16;
            As[lk * 132 + row] = kin ? A[(size_t)(m0 + row) * K + k] : 0.0f;
        }
#pragma unroll
        for (int p = 0; p < 8; ++p) {
            int row = lr + p * 16;
            int n = n0 + row;
            Bs[lk * 132 + row] = (kin && n < N) ? W[(size_t)n * K + k] : 0.0f;
        }
        __syncthreads();

#pragma unroll
        for (int kk = 0; kk < BK; ++kk) {
            u64 a[4];
#pragma unroll
            for (int p = 0; p < 4; ++p)
                a[p] = *(const u64*)&As[kk * 132 + ty * 8 + p * 2];
#pragma unroll
            for (int c = 0; c < 8; ++c) {
                u64 bb = dup2(Bs[kk * 132 + tx + 16 * c]);
#pragma unroll
                for (int p = 0; p < 4; ++p) acc[p][c] = ffma2(a[p], bb, acc[p][c]);
            }
        }
        __syncthreads();
    }

#pragma unroll
    for (int c = 0; c < 8; ++c) {
        int n = n0 + tx + 16 * c;
        if (n >= N) continue;
        float bv = bias[n];
#pragma unroll
        for (int p = 0; p < 4; ++p) {
            float2 v = unpack2(acc[p][c]);
            int m = m0 + ty * 8 + p * 2;
            C[(size_t)m * N + n]       = v.x + bv;
            C[(size_t)(m + 1) * N + n] = v.y + bv;
        }
    }
}

// ---------------------------------------------------------------------------
// One LSTM timestep, fused GEMM + gates.
// Block: all 128 batch rows x 8 hidden units (x 4 gates = 32 GEMM cols).
// 128 threads; thread = 8 batch rows (4 f32x2 pairs) x 4 gates at fixed j.
__global__ __launch_bounds__(128) void lstm_step(
    const float* __restrict__ xg_t,   // [128, 4H] this timestep's input gates
    const float* __restrict__ h_prev, // [128, H]
    const float* __restrict__ W_hh,   // [4H, H]
    float* __restrict__ h_out,        // [128, H]
    float* __restrict__ c_state,      // [128, H]
    int H)
{
    __shared__ float As[16 * 132];    // h tile: [k][batch 0..127]
    __shared__ float Bs[16 * 34];     // W tile: [k][col 0..31], col = gate*8 + j

    const int tid = threadIdx.x;
    const int hh0 = blockIdx.x * 8;
    const int j  = tid & 7;           // hidden unit within tile
    const int rg = tid >> 3;          // 0..15, rows rg*8..rg*8+7
    const int lk = tid & 15;          // loader k
    const int lr = tid >> 4;          // 0..7

    u64 acc[4][4];                    // [rowpair][gate]
#pragma unroll
    for (int p = 0; p < 4; ++p)
#pragma unroll
        for (int g = 0; g < 4; ++g) acc[p][g] = 0ull;

    for (int k0 = 0; k0 < H; k0 += 16) {
        const int k = k0 + lk;
        const bool kin = (k < H);
#pragma unroll
        for (int p = 0; p < 16; ++p) {
            int row = lr + p * 8;
            As[lk * 132 + row] = kin ? h_prev[(size_t)row * H + k] : 0.0f;
        }
#pragma unroll
        for (int p = 0; p < 4; ++p) {
            int col = lr + p * 8;
            int g = col >> 3, jj = col & 7;
            float v = 0.0f;
            if (kin && (hh0 + jj) < H)
                v = W_hh[(size_t)(g * H + hh0 + jj) * H + k];
            Bs[lk * 34 + col] = v;
        }
        __syncthreads();

#pragma unroll
        for (int kk = 0; kk < 16; ++kk) {
            u64 a[4];
#pragma unroll
            for (int p = 0; p < 4; ++p)
                a[p] = *(const u64*)&As[kk * 132 + rg * 8 + p * 2];
#pragma unroll
            for (int g = 0; g < 4; ++g) {
                u64 bb = dup2(Bs[kk * 34 + g * 8 + j]);
#pragma unroll
                for (int p = 0; p < 4; ++p) acc[p][g] = ffma2(a[p], bb, acc[p][g]);
            }
        }
        __syncthreads();
    }

    const int hh = hh0 + j;
    if (hh < H) {
        const size_t H4 = (size_t)4 * H;
#pragma unroll
        for (int p = 0; p < 4; ++p) {
            float2 vi = unpack2(acc[p][0]);
            float2 vf = unpack2(acc[p][1]);
            float2 vg = unpack2(acc[p][2]);
            float2 vo = unpack2(acc[p][3]);
#pragma unroll
            for (int half = 0; half < 2; ++half) {
                int b = rg * 8 + p * 2 + half;
                const float* xgb = xg_t + (size_t)b * H4 + hh;
                float pi = (half ? vi.y : vi.x) + xgb[0];
                float pf = (half ? vf.y : vf.x) + xgb[H];
                float pg = (half ? vg.y : vg.x) + xgb[2 * H];
                float po = (half ? vo.y : vo.x) + xgb[3 * H];
                float si = 1.0f / (1.0f + expf(-pi));
                float sf = 1.0f / (1.0f + expf(-pf));
                float so = 1.0f / (1.0f + expf(-po));
                float tg = tanhf(pg);
                size_t idx = (size_t)b * H + hh;
                float cc = sf * c_state[idx] + si * tg;
                c_state[idx] = cc;
                h_out[idx] = so * tanhf(cc);
            }
        }
    }
}

// ---------------------------------------------------------------------------
extern "C" void kernel_launch(void* const* d_in, const int* in_sizes, int n_in,
                              void* d_out, int out_size) {
    const int*   tokens = (const int*)d_in[0];
    const float* emb    = (const float*)d_in[1];
    const float* Wih[3] = {(const float*)d_in[2], (const float*)d_in[5], (const float*)d_in[8]};
    const float* Whh[3] = {(const float*)d_in[3], (const float*)d_in[6], (const float*)d_in[9]};
    const float* bb[3]  = {(const float*)d_in[4], (const float*)d_in[7], (const float*)d_in[10]};
    float* out = (float*)d_out;

    float *x0, *xg, *cst, *h0;
    cudaGetSymbolAddress((void**)&x0,  g_x0);
    cudaGetSymbolAddress((void**)&xg,  g_xg);
    cudaGetSymbolAddress((void**)&cst, g_c);
    cudaGetSymbolAddress((void**)&h0,  g_h0);

    // embedding lookup -> g_x0 [25600, 400]
    embed_kernel<<<MROWS, 128>>>(tokens, emb, x0);
    // zero initial hidden state (read-only afterwards)
    zero_kernel<<<(BATCH * 1150 + 255) / 256, 256>>>(h0, BATCH * 1150);

    const int Hs[3] = {1150, 1150, 400};
    const int Ks[3] = {400, 1150, 1150};
    const size_t outoff[3] = {0, (size_t)T_SEQ * BATCH * 1150, (size_t)T_SEQ * BATCH * 1150 * 2};

    const float* Ain = x0;
    for (int l = 0; l < 3; ++l) {
        const int H = Hs[l], K = Ks[l], N = 4 * H;

        // reset cell state for this layer
        zero_kernel<<<(BATCH * H + 255) / 256, 256>>>(cst, BATCH * H);

        // xg = Ain @ W_ih^T + b   [25600, 4H]
        dim3 grid((N + 127) / 128, MROWS / 128);
        sgemm_nt_bias<<<grid, 256>>>(Ain, Wih[l], bb[l], xg, MROWS, N, K);

        float* outl = out + outoff[l];
        for (int t = 0; t < T_SEQ; ++t) {
            const float* hp = (t == 0) ? h0 : (outl + (size_t)(t - 1) * BATCH * H);
            lstm_step<<<(H + 7) / 8, 128>>>(xg + (size_t)t * BATCH * N, hp,
                                            Whh[l], outl + (size_t)t * BATCH * H,
                                            cst, H);
        }
        Ain = outl;
    }
}

// round 2
// speedup vs baseline: 1.0288x; 1.0288x over previous
#include <cuda_runtime.h>
#include <math.h>

typedef unsigned long long u64;

// ---- packed f32x2 FMA helpers (Blackwell sm_100+) ----
__device__ __forceinline__ u64 dup2(float x) {
    u64 r; asm("mov.b64 %0, {%1,%2};" : "=l"(r) : "f"(x), "f"(x)); return r;
}
__device__ __forceinline__ u64 ffma2(u64 a, u64 b, u64 c) {
    u64 d; asm("fma.rn.f32x2 %0, %1, %2, %3;" : "=l"(d) : "l"(a), "l"(b), "l"(c)); return d;
}
__device__ __forceinline__ float2 unpack2(u64 v) {
    float2 f; asm("mov.b64 {%0,%1}, %2;" : "=f"(f.x), "=f"(f.y) : "l"(v)); return f;
}

#define T_SEQ 200
#define BATCH 128
#define MROWS (T_SEQ * BATCH)   // 25600

// ---- device-global scratch (no allocations allowed) ----
__device__ float g_x0[MROWS * 400];             // embedded input
__device__ float g_xg[(size_t)MROWS * 4600];    // per-layer xg buffer
__device__ float g_c[BATCH * 1150];             // LSTM cell state
__device__ float g_h0[BATCH * 1150];            // zero h for t=0

// ---------------------------------------------------------------------------
__global__ void zero_kernel(float* __restrict__ p, int n) {
    int i = blockIdx.x * blockDim.x + threadIdx.x;
    if (i < n) p[i] = 0.0f;
}

// ---------------------------------------------------------------------------
__global__ void embed_kernel(const int* __restrict__ tokens,
                             const float* __restrict__ emb,
                             float* __restrict__ x) {
    int row = blockIdx.x;
    int tok = tokens[row];
    const float4* s = (const float4*)(emb + (size_t)tok * 400);
    float4* d = (float4*)(x + (size_t)row * 400);
    for (int i = threadIdx.x; i < 100; i += blockDim.x) d[i] = s[i];
}

// ---------------------------------------------------------------------------
// C[M,N] = A[M,K] @ W[N,K]^T + bias[N]
// 128x128 tile, BK=16, 256 threads, 8x8/thread, double-buffered smem.
#define BK 16
#define AST 130   // smem row stride (conflict-free, 8B aligned)
__global__ __launch_bounds__(256) void sgemm_nt_bias(
    const float* __restrict__ A, const float* __restrict__ W,
    const float* __restrict__ bias, float* __restrict__ C,
    int M, int N, int K)
{
    __shared__ float As[2 * BK * AST];
    __shared__ float Bs[2 * BK * AST];

    const int tid = threadIdx.x;
    const int m0 = blockIdx.y * 128;
    const int n0 = blockIdx.x * 128;
    const int tx = tid & 15;
    const int ty = tid >> 4;
    const int lk = tid & 15;       // loader k
    const int lr = tid >> 4;       // loader row base (0..15)

    u64 acc[4][8];
#pragma unroll
    for (int p = 0; p < 4; ++p)
#pragma unroll
        for (int c = 0; c < 8; ++c) acc[p][c] = 0ull;

    const int nt = (K + BK - 1) / BK;
    float ra[8], rb[8];

    // prologue: tile 0 (k = lk < 16 <= K always valid)
    {
        const int k = lk;
#pragma unroll
        for (int p = 0; p < 8; ++p) {
            int row = lr + p * 16;
            ra[p] = A[(size_t)(m0 + row) * K + k];
            int n = n0 + row;
            rb[p] = (n < N) ? W[(size_t)n * K + k] : 0.0f;
        }
#pragma unroll
        for (int p = 0; p < 8; ++p) {
            As[lk * AST + lr + p * 16] = ra[p];
            Bs[lk * AST + lr + p * 16] = rb[p];
        }
    }
    __syncthreads();

    for (int i = 0; i < nt; ++i) {
        const int cur = i & 1;
        const bool more = (i + 1 < nt);
        if (more) {
            const int k = (i + 1) * BK + lk;
            const bool kin = (k < K);
#pragma unroll
            for (int p = 0; p < 8; ++p) {
                int row = lr + p * 16;
                ra[p] = kin ? A[(size_t)(m0 + row) * K + k] : 0.0f;
                int n = n0 + row;
                rb[p] = (kin && n < N) ? W[(size_t)n * K + k] : 0.0f;
            }
        }

        const float* Ac = As + cur * BK * AST;
        const float* Bc = Bs + cur * BK * AST;
#pragma unroll
        for (int kk = 0; kk < BK; ++kk) {
            u64 a[4];
#pragma unroll
            for (int p = 0; p < 4; ++p)
                a[p] = *(const u64*)&Ac[kk * AST + ty * 8 + p * 2];
#pragma unroll
            for (int c = 0; c < 8; ++c) {
                u64 bb = dup2(Bc[kk * AST + tx + 16 * c]);
#pragma unroll
                for (int p = 0; p < 4; ++p) acc[p][c] = ffma2(a[p], bb, acc[p][c]);
            }
        }

        if (more) {
            float* An = As + (1 - cur) * BK * AST;
            float* Bn = Bs + (1 - cur) * BK * AST;
#pragma unroll
            for (int p = 0; p < 8; ++p) {
                An[lk * AST + lr + p * 16] = ra[p];
                Bn[lk * AST + lr + p * 16] = rb[p];
            }
        }
        __syncthreads();
    }

#pragma unroll
    for (int c = 0; c < 8; ++c) {
        int n = n0 + tx + 16 * c;
        if (n >= N) continue;
        float bv = bias[n];
#pragma unroll
        for (int p = 0; p < 4; ++p) {
            float2 v = unpack2(acc[p][c]);
            int m = m0 + ty * 8 + p * 2;
            C[(size_t)m * N + n]       = v.x + bv;
            C[(size_t)(m + 1) * N + n] = v.y + bv;
        }
    }
}

// ---------------------------------------------------------------------------
// One LSTM timestep, fused GEMM + gates. Double-buffered, batch-split.
// Block: 64 batch rows (blockIdx.y half) x 8 hidden units (32 gemm cols).
// 128 threads: thread = 4 batch rows x 4 gates at fixed unit j.
#define LAST 66   // As stride: 64 rows + pad (conflict-free, 8B aligned)
#define LBST 33   // Bs stride
__global__ __launch_bounds__(128) void lstm_step(
    const float* __restrict__ xg_t,   // [128, 4H]
    const float* __restrict__ h_prev, // [128, H]
    const float* __restrict__ W_hh,   // [4H, H]
    float* __restrict__ h_out,        // [128, H]
    float* __restrict__ c_state,      // [128, H]
    int H)
{
    __shared__ float As[2 * 16 * LAST];
    __shared__ float Bs[2 * 16 * LBST];

    const int tid = threadIdx.x;
    const int hh0 = blockIdx.x * 8;
    const int rowoff = blockIdx.y * 64;
    const int j  = tid & 7;           // hidden unit in tile
    const int rg = tid >> 3;          // 0..15 -> rows rg*4..rg*4+3
    const int lk = tid & 15;          // loader k
    const int lr = tid >> 4;          // 0..7

    u64 acc[2][4];
#pragma unroll
    for (int p = 0; p < 2; ++p)
#pragma unroll
        for (int g = 0; g < 4; ++g) acc[p][g] = 0ull;

    const int nt = (H + 15) >> 4;
    float ra[8], rbw[4];

    // prologue: tile 0
    {
        const int k = lk;
#pragma unroll
        for (int p = 0; p < 8; ++p)
            ra[p] = h_prev[(size_t)(rowoff + lr + p * 8) * H + k];
#pragma unroll
        for (int p = 0; p < 4; ++p) {
            int col = lr + p * 8;
            int g = col >> 3, jj = col & 7;
            rbw[p] = (hh0 + jj < H) ? W_hh[(size_t)(g * H + hh0 + jj) * H + k] : 0.0f;
        }
#pragma unroll
        for (int p = 0; p < 8; ++p) As[lk * LAST + lr + p * 8] = ra[p];
#pragma unroll
        for (int p = 0; p < 4; ++p) Bs[lk * LBST + lr + p * 8] = rbw[p];
    }
    __syncthreads();

    for (int i = 0; i < nt; ++i) {
        const int cur = i & 1;
        const bool more = (i + 1 < nt);
        if (more) {
            const int k = (i + 1) * 16 + lk;
            const bool kin = (k < H);
#pragma unroll
            for (int p = 0; p < 8; ++p)
                ra[p] = kin ? h_prev[(size_t)(rowoff + lr + p * 8) * H + k] : 0.0f;
#pragma unroll
            for (int p = 0; p < 4; ++p) {
                int col = lr + p * 8;
                int g = col >> 3, jj = col & 7;
                rbw[p] = (kin && hh0 + jj < H)
                       ? W_hh[(size_t)(g * H + hh0 + jj) * H + k] : 0.0f;
            }
        }

        const float* Ac = As + cur * 16 * LAST;
        const float* Bc = Bs + cur * 16 * LBST;
#pragma unroll
        for (int kk = 0; kk < 16; ++kk) {
            u64 a0 = *(const u64*)&Ac[kk * LAST + rg * 4];
            u64 a1 = *(const u64*)&Ac[kk * LAST + rg * 4 + 2];
#pragma unroll
            for (int g = 0; g < 4; ++g) {
                u64 bb = dup2(Bc[kk * LBST + g * 8 + j]);
                acc[0][g] = ffma2(a0, bb, acc[0][g]);
                acc[1][g] = ffma2(a1, bb, acc[1][g]);
            }
        }

        if (more) {
            float* An = As + (1 - cur) * 16 * LAST;
            float* Bn = Bs + (1 - cur) * 16 * LBST;
#pragma unroll
            for (int p = 0; p < 8; ++p) An[lk * LAST + lr + p * 8] = ra[p];
#pragma unroll
            for (int p = 0; p < 4; ++p) Bn[lk * LBST + lr + p * 8] = rbw[p];
        }
        __syncthreads();
    }

    const int hh = hh0 + j;
    if (hh < H) {
        const size_t H4 = (size_t)4 * H;
#pragma unroll
        for (int p = 0; p < 2; ++p) {
            float2 vi = unpack2(acc[p][0]);
            float2 vf = unpack2(acc[p][1]);
            float2 vg = unpack2(acc[p][2]);
            float2 vo = unpack2(acc[p][3]);
#pragma unroll
            for (int half = 0; half < 2; ++half) {
                int b = rowoff + rg * 4 + p * 2 + half;
                const float* xgb = xg_t + (size_t)b * H4 + hh;
                float pi = (half ? vi.y : vi.x) + xgb[0];
                float pf = (half ? vf.y : vf.x) + xgb[H];
                float pg = (half ? vg.y : vg.x) + xgb[2 * H];
                float po = (half ? vo.y : vo.x) + xgb[3 * H];
                float si = 1.0f / (1.0f + expf(-pi));
                float sf = 1.0f / (1.0f + expf(-pf));
                float so = 1.0f / (1.0f + expf(-po));
                float tg = tanhf(pg);
                size_t idx = (size_t)b * H + hh;
                float cc = sf * c_state[idx] + si * tg;
                c_state[idx] = cc;
                h_out[idx] = so * tanhf(cc);
            }
        }
    }
}

// ---------------------------------------------------------------------------
extern "C" void kernel_launch(void* const* d_in, const int* in_sizes, int n_in,
                              void* d_out, int out_size) {
    const int*   tokens = (const int*)d_in[0];
    const float* emb    = (const float*)d_in[1];
    const float* Wih[3] = {(const float*)d_in[2], (const float*)d_in[5], (const float*)d_in[8]};
    const float* Whh[3] = {(const float*)d_in[3], (const float*)d_in[6], (const float*)d_in[9]};
    const float* bb[3]  = {(const float*)d_in[4], (const float*)d_in[7], (const float*)d_in[10]};
    float* out = (float*)d_out;

    float *x0, *xg, *cst, *h0;
    cudaGetSymbolAddress((void**)&x0,  g_x0);
    cudaGetSymbolAddress((void**)&xg,  g_xg);
    cudaGetSymbolAddress((void**)&cst, g_c);
    cudaGetSymbolAddress((void**)&h0,  g_h0);

    embed_kernel<<<MROWS, 128>>>(tokens, emb, x0);
    zero_kernel<<<(BATCH * 1150 + 255) / 256, 256>>>(h0, BATCH * 1150);

    const int Hs[3] = {1150, 1150, 400};
    const int Ks[3] = {400, 1150, 1150};
    const size_t outoff[3] = {0, (size_t)T_SEQ * BATCH * 1150, (size_t)T_SEQ * BATCH * 1150 * 2};

    const float* Ain = x0;
    for (int l = 0; l < 3; ++l) {
        const int H = Hs[l], K = Ks[l], N = 4 * H;

        zero_kernel<<<(BATCH * H + 255) / 256, 256>>>(cst, BATCH * H);

        dim3 grid((N + 127) / 128, MROWS / 128);
        sgemm_nt_bias<<<grid, 256>>>(Ain, Wih[l], bb[l], xg, MROWS, N, K);

        float* outl = out + outoff[l];
        dim3 sgrid((H + 7) / 8, 2);
        for (int t = 0; t < T_SEQ; ++t) {
            const float* hp = (t == 0) ? h0 : (outl + (size_t)(t - 1) * BATCH * H);
            lstm_step<<<sgrid, 128>>>(xg + (size_t)t * BATCH * N, hp,
                                      Whh[l], outl + (size_t)t * BATCH * H,
                                      cst, H);
        }
        Ain = outl;
    }
}